// round 12
// baseline (speedup 1.0000x reference)
#include <cuda_runtime.h>
#include <cuda_bf16.h>
#include <math.h>
#include <stdint.h>

// ---------------------------------------------------------------------------
// Problem constants
// ---------------------------------------------------------------------------
#define B_     4
#define T1_    2048
#define JT_    512
#define DIM_   1024
#define INNER_ 512
#define DFF_   4096
#define H_     8
#define DH_    64

// ---------------------------------------------------------------------------
// Scratch (device globals; no allocation allowed)
// ---------------------------------------------------------------------------
__device__ float g_q [(size_t)B_*T1_*INNER_];
__device__ float g_kv[(size_t)B_*JT_*2*INNER_];
__device__ float g_x [(size_t)B_*T1_*DIM_];
__device__ __nv_bfloat16 g_ln_h [(size_t)B_*T1_*DIM_];
__device__ __nv_bfloat16 g_ao_h [(size_t)B_*T1_*INNER_];
__device__ __nv_bfloat16 g_h_h  [(size_t)B_*T1_*DFF_];
__device__ __nv_bfloat16 g_kvo_h[(size_t)B_*JT_*DIM_];
__device__ __nv_bfloat16 g_wq_t [(size_t)INNER_*DIM_];     // weights, [N][K] bf16
__device__ __nv_bfloat16 g_wkv_t[(size_t)2*INNER_*DIM_];
__device__ __nv_bfloat16 g_wout_t[(size_t)DIM_*INNER_];
__device__ __nv_bfloat16 g_w1_t [(size_t)DFF_*DIM_];
__device__ __nv_bfloat16 g_w2_t [(size_t)DIM_*DFF_];
__device__ unsigned int g_keep[(size_t)B_*T1_*JT_/32];     // packed amask&kvmask bits
__device__ int g_mask_mode;

// ---------------------------------------------------------------------------
// Mask dtype detection (bool may arrive as uint8 / int32 / float32)
// ---------------------------------------------------------------------------
__global__ void detect_mask_kernel(const unsigned int* __restrict__ w, int nwords)
{
    __shared__ int f_u8, f_f32;
    if (threadIdx.x == 0) { f_u8 = 0; f_f32 = 0; }
    __syncthreads();
    int u8 = 0, f32 = 0;
    for (int i = threadIdx.x; i < nwords; i += blockDim.x) {
        unsigned int x = w[i];
        if (x == 0x3F800000u)            f32 = 1;
        else if (x != 0u && x != 1u)     u8  = 1;
    }
    if (u8)  atomicOr(&f_u8, 1);
    if (f32) atomicOr(&f_f32, 1);
    __syncthreads();
    if (threadIdx.x == 0)
        g_mask_mode = f_u8 ? 0 : (f_f32 ? 2 : 1);
}

__device__ __forceinline__ bool read_mask(const void* p, size_t i, int mode)
{
    if (mode == 1) return ((const int*)p)[i] != 0;
    if (mode == 2) return ((const float*)p)[i] != 0.0f;
    return ((const unsigned char*)p)[i] != 0;
}

// ---------------------------------------------------------------------------
// Pack keep bits: bit e of g_keep = amask[e] && kvmask[b, j]. Ballot-packed.
// ---------------------------------------------------------------------------
__global__ __launch_bounds__(256) void pack_keep_kernel(
    const void* __restrict__ amask, const void* __restrict__ kvmask,
    unsigned int* __restrict__ out)
{
    const size_t e = (size_t)blockIdx.x * 256 + threadIdx.x;
    const int mode = g_mask_mode;
    const int b = (int)(e / ((size_t)T1_ * JT_));
    const int j = (int)(e % JT_);
    const bool k = read_mask(amask, e, mode) &&
                   read_mask(kvmask, (size_t)b * JT_ + j, mode);
    const unsigned bal = __ballot_sync(0xffffffffu, k);
    if ((threadIdx.x & 31) == 0) out[e >> 5] = bal;
}

// ---------------------------------------------------------------------------
// Conversion pre-kernels
// ---------------------------------------------------------------------------
__global__ __launch_bounds__(256) void f32_to_bf16_kernel(
    const float* __restrict__ in, __nv_bfloat16* __restrict__ out, int n4)
{
    const int i = blockIdx.x * 256 + threadIdx.x;
    if (i < n4) {
        const float4 v = reinterpret_cast<const float4*>(in)[i];
        __nv_bfloat162* o = reinterpret_cast<__nv_bfloat162*>(out) + i * 2;
        o[0] = __floats2bfloat162_rn(v.x, v.y);
        o[1] = __floats2bfloat162_rn(v.z, v.w);
    }
}

// in: f32 [K][N]  ->  out: bf16 [N][K]
__global__ __launch_bounds__(256) void transpose_bf16_kernel(
    const float* __restrict__ in, __nv_bfloat16* __restrict__ out, int K, int N)
{
    __shared__ float tile[32][33];
    const int n0 = blockIdx.x * 32, k0 = blockIdx.y * 32;
    const int tx = threadIdx.x, ty = threadIdx.y;
    #pragma unroll
    for (int r = ty; r < 32; r += 8)
        tile[r][tx] = in[(size_t)(k0 + r) * N + n0 + tx];
    __syncthreads();
    #pragma unroll
    for (int r = ty; r < 32; r += 8)
        out[(size_t)(n0 + r) * K + k0 + tx] = __float2bfloat16(tile[tx][r]);
}

// ---------------------------------------------------------------------------
// LayerNorm (bf16 out), vectorized float4 path. One block per row, 256 thr.
// ---------------------------------------------------------------------------
__global__ __launch_bounds__(256) void ln_kernel(
    const float* __restrict__ x, const float* __restrict__ gw,
    const float* __restrict__ bw, __nv_bfloat16* __restrict__ y)
{
    const int row = blockIdx.x;
    const float4 v = reinterpret_cast<const float4*>(
        x + (size_t)row * DIM_)[threadIdx.x];
    float s  = v.x + v.y + v.z + v.w;
    float s2 = v.x * v.x + v.y * v.y + v.z * v.z + v.w * v.w;
    #pragma unroll
    for (int o = 16; o; o >>= 1) {
        s  += __shfl_xor_sync(0xffffffffu, s,  o);
        s2 += __shfl_xor_sync(0xffffffffu, s2, o);
    }
    __shared__ float sh[2][8];
    const int warp = threadIdx.x >> 5, lane = threadIdx.x & 31;
    if (lane == 0) { sh[0][warp] = s; sh[1][warp] = s2; }
    __syncthreads();
    if (threadIdx.x == 0) {
        float S = 0.f, S2 = 0.f;
        #pragma unroll
        for (int w = 0; w < 8; w++) { S += sh[0][w]; S2 += sh[1][w]; }
        const float mu  = S  * (1.0f / DIM_);
        const float var = S2 * (1.0f / DIM_) - mu * mu;
        sh[0][0] = mu;
        sh[1][0] = rsqrtf(var + 1e-5f);
    }
    __syncthreads();
    const float mu = sh[0][0], inv = sh[1][0];
    const float4 gv = reinterpret_cast<const float4*>(gw)[threadIdx.x];
    const float4 bv = reinterpret_cast<const float4*>(bw)[threadIdx.x];
    __nv_bfloat162* yr = reinterpret_cast<__nv_bfloat162*>(
        y + (size_t)row * DIM_) + threadIdx.x * 2;
    yr[0] = __floats2bfloat162_rn((v.x - mu) * inv * gv.x + bv.x,
                                  (v.y - mu) * inv * gv.y + bv.y);
    yr[1] = __floats2bfloat162_rn((v.z - mu) * inv * gv.z + bv.z,
                                  (v.w - mu) * inv * gv.w + bv.w);
}

// ---------------------------------------------------------------------------
// helpers
// ---------------------------------------------------------------------------
__device__ __forceinline__ float tf32r(float x)
{
    uint32_t r;
    asm("cvt.rna.tf32.f32 %0, %1;" : "=r"(r) : "f"(x));
    return __uint_as_float(r);
}

__device__ __forceinline__ void mma_tf32(
    float* c, const uint32_t* a, const uint32_t* b)
{
    asm volatile(
        "mma.sync.aligned.m16n8k8.row.col.f32.tf32.tf32.f32 "
        "{%0,%1,%2,%3},{%4,%5,%6,%7},{%8,%9},{%0,%1,%2,%3};"
        : "+f"(c[0]), "+f"(c[1]), "+f"(c[2]), "+f"(c[3])
        : "r"(a[0]), "r"(a[1]), "r"(a[2]), "r"(a[3]), "r"(b[0]), "r"(b[1]));
}

__device__ __forceinline__ void mma_bf16(
    float* c, const uint32_t* a, const uint32_t* b)
{
    asm volatile(
        "mma.sync.aligned.m16n8k16.row.col.f32.bf16.bf16.f32 "
        "{%0,%1,%2,%3},{%4,%5,%6,%7},{%8,%9},{%0,%1,%2,%3};"
        : "+f"(c[0]), "+f"(c[1]), "+f"(c[2]), "+f"(c[3])
        : "r"(a[0]), "r"(a[1]), "r"(a[2]), "r"(a[3]), "r"(b[0]), "r"(b[1]));
}

__device__ __forceinline__ void cpa16(void* dst_smem, const void* src_gmem)
{
    uint32_t d = (uint32_t)__cvta_generic_to_shared(dst_smem);
    asm volatile("cp.async.cg.shared.global [%0], [%1], 16;"
                 :: "r"(d), "l"(src_gmem));
}

__device__ __forceinline__ uint32_t smem_u32(const void* p)
{
    uint32_t a;
    asm("{ .reg .u64 t; cvta.to.shared.u64 t, %1; cvt.u32.u64 %0, t; }"
        : "=r"(a) : "l"(p));
    return a;
}

__device__ __forceinline__ void ldsm_x4(
    uint32_t& r0, uint32_t& r1, uint32_t& r2, uint32_t& r3, uint32_t addr)
{
    asm volatile("ldmatrix.sync.aligned.m8n8.x4.shared.b16 {%0,%1,%2,%3}, [%4];"
                 : "=r"(r0), "=r"(r1), "=r"(r2), "=r"(r3) : "r"(addr));
}

// ---------------------------------------------------------------------------
// bf16 tensor-core GEMM v3: CTA tile 128x256, warp tile 32x128.
// 256 threads = 8 warps (4m x 2n). Fragment loads via ldmatrix.x4; per K-32
// chunk per warp: 4 A-LDSM + 16 B-LDSM + 64 mma (ratio 3.2:1 vs 2.7:1 at
// 128x128). K-accumulation order per output element unchanged -> results
// bit-identical to the R10 kernel. smem 61440 B double-buffered.
// EPI: 0 none, 1 exact GELU, 2 v*tanh(*gate)+res. OBF: bf16 C output.
// ---------------------------------------------------------------------------
#define P_SM 40
#define A_ELE (128 * P_SM)
#define B_ELE (256 * P_SM)
#define GEMM_SMEM (2 * (A_ELE + B_ELE) * (int)sizeof(__nv_bfloat16))  // 61440

template <int EPI, int OBF>
__global__ __launch_bounds__(256, 1) void bf16_gemm_kernel(
    const __nv_bfloat16* __restrict__ A, const __nv_bfloat16* __restrict__ Bt,
    void* __restrict__ Cv, int M, int N, int K,
    const float* __restrict__ gate, const float* __restrict__ res)
{
    extern __shared__ __nv_bfloat16 smh[];
    __nv_bfloat16* Abuf[2] = { smh,              smh + A_ELE + B_ELE };
    __nv_bfloat16* Bbuf[2] = { smh + A_ELE,      smh + 2 * A_ELE + B_ELE };
    const uint32_t smb = smem_u32(smh);
    const uint32_t Ab[2] = { smb,                        smb + 2u * (A_ELE + B_ELE) };
    const uint32_t Bb[2] = { smb + 2u * A_ELE,           smb + 2u * (2 * A_ELE + B_ELE) };

    const int tid  = threadIdx.x;
    const int warp = tid >> 5, lane = tid & 31;
    const int wm = warp >> 1, wn = warp & 1;
    const int g = lane >> 2, q4 = lane & 3;
    const int row0 = blockIdx.y << 7, col0 = blockIdx.x << 8;

    // staging: A 128 rows x 64B (2 thr/row, 2 x 16B each); B 256 rows x 64B
    // (1 thr/row, 4 x 16B each)
    const int sra = tid >> 1, sca = (tid & 1) << 1;
    const __nv_bfloat16* Ag = A  + (size_t)(row0 + sra) * K + sca * 8;
    const __nv_bfloat16* Bg = Bt + (size_t)(col0 + tid) * K;

    // ldmatrix address components
    const int a_row0 = wm * 32 + (lane & 15);
    const int a_col0 = (lane >> 4) << 3;
    const int b_row0 = wn * 128 + ((lane >> 4) << 3) + (lane & 7);
    const int b_col0 = ((lane >> 3) & 1) << 3;

    float c[2][16][4];
    #pragma unroll
    for (int i = 0; i < 2; i++)
        #pragma unroll
        for (int j = 0; j < 16; j++)
            #pragma unroll
            for (int q = 0; q < 4; q++) c[i][j][q] = 0.f;

    const int iters = K >> 5;

    cpa16(Abuf[0] + sra * P_SM + sca * 8,     Ag);
    cpa16(Abuf[0] + sra * P_SM + sca * 8 + 8, Ag + 8);
    #pragma unroll
    for (int cchunk = 0; cchunk < 4; cchunk++)
        cpa16(Bbuf[0] + tid * P_SM + cchunk * 8, Bg + cchunk * 8);
    asm volatile("cp.async.commit_group;");

    for (int t = 0; t < iters; t++) {
        if (t + 1 < iters) {
            const int k1 = (t + 1) << 5;
            __nv_bfloat16* Ad = Abuf[(t + 1) & 1];
            __nv_bfloat16* Bd = Bbuf[(t + 1) & 1];
            cpa16(Ad + sra * P_SM + sca * 8,     Ag + k1);
            cpa16(Ad + sra * P_SM + sca * 8 + 8, Ag + k1 + 8);
            #pragma unroll
            for (int cchunk = 0; cchunk < 4; cchunk++)
                cpa16(Bd + tid * P_SM + cchunk * 8, Bg + k1 + cchunk * 8);
            asm volatile("cp.async.commit_group;");
            asm volatile("cp.async.wait_group 1;");
        } else {
            asm volatile("cp.async.wait_group 0;");
        }
        __syncthreads();

        const uint32_t sA = Ab[t & 1];
        const uint32_t sB = Bb[t & 1];
        #pragma unroll
        for (int ks = 0; ks < 2; ks++) {
            uint32_t a[2][4];
            #pragma unroll
            for (int i = 0; i < 2; i++)
                ldsm_x4(a[i][0], a[i][1], a[i][2], a[i][3],
                        sA + (uint32_t)(((a_row0 + i * 16) * P_SM
                                         + ks * 16 + a_col0) * 2));
            #pragma unroll
            for (int jp = 0; jp < 8; jp++) {
                uint32_t r0, r1, r2, r3;
                ldsm_x4(r0, r1, r2, r3,
                        sB + (uint32_t)(((b_row0 + jp * 16) * P_SM
                                         + ks * 16 + b_col0) * 2));
                uint32_t b0[2] = { r0, r1 }, b1[2] = { r2, r3 };
                #pragma unroll
                for (int i = 0; i < 2; i++) {
                    mma_bf16(c[i][2 * jp],     a[i], b0);
                    mma_bf16(c[i][2 * jp + 1], a[i], b1);
                }
            }
        }
        __syncthreads();
    }

    float gt = 0.f;
    if (EPI == 2) gt = tanhf(gate[0]);
    #pragma unroll
    for (int i = 0; i < 2; i++) {
        const int r_lo = row0 + wm * 32 + i * 16 + g;
        #pragma unroll
        for (int j = 0; j < 16; j++) {
            const int cc = col0 + wn * 128 + j * 8 + 2 * q4;
            #pragma unroll
            for (int half = 0; half < 2; half++) {
                const size_t rr = (size_t)(r_lo + 8 * half);
                float v0 = c[i][j][2 * half + 0];
                float v1 = c[i][j][2 * half + 1];
                if (EPI == 1) {
                    v0 = 0.5f * v0 * (1.0f + erff(v0 * 0.70710678118654752f));
                    v1 = 0.5f * v1 * (1.0f + erff(v1 * 0.70710678118654752f));
                }
                if (EPI == 2) {
                    const float2 rv =
                        *reinterpret_cast<const float2*>(res + rr * N + cc);
                    v0 = v0 * gt + rv.x;
                    v1 = v1 * gt + rv.y;
                }
                if (OBF) {
                    *reinterpret_cast<__nv_bfloat162*>(
                        (__nv_bfloat16*)Cv + rr * N + cc) =
                        __floats2bfloat162_rn(v0, v1);
                } else {
                    *reinterpret_cast<float2*>((float*)Cv + rr * N + cc) =
                        make_float2(v0, v1);
                }
            }
        }
    }
}

// ---------------------------------------------------------------------------
// mma-based fused masked flash attention (128 rows/CTA, bitmask) — R10.
// ---------------------------------------------------------------------------
#define AT_PAD  68
#define ATQ     (128 * AT_PAD)
#define ATTN3_SMEM (3 * ATQ * 4 + 128 * 4 * 4)

__global__ __launch_bounds__(256) void attn_mma_kernel(
    const float* __restrict__ Q,
    const float* __restrict__ KV,
    const unsigned int* __restrict__ KB,
    const float* __restrict__ qmask,
    __nv_bfloat16* __restrict__ AO)
{
    extern __shared__ float sm[];
    float* Qs = sm;
    float* Ks = Qs + ATQ;
    float* Vs = Ks + ATQ;
    unsigned int* keepw = (unsigned int*)(Vs + ATQ);

    const int i0 = blockIdx.x * 128;
    const int h  = blockIdx.y;
    const int b  = blockIdx.z;
    const int tid  = threadIdx.x;
    const int warp = tid >> 5, lane = tid & 31;
    const int g = lane >> 2, q4 = lane & 3;
    const int row_g = warp * 16 + g;

    for (int t = tid; t < 128 * 16; t += 256) {
        const int rr = t >> 4, c4 = (t & 15) << 2;
        const float4 v = *reinterpret_cast<const float4*>(
            Q + ((size_t)(b * T1_ + i0 + rr)) * INNER_ + h * DH_ + c4);
        float* d = Qs + rr * AT_PAD + c4;
        d[0] = v.x * 0.125f; d[1] = v.y * 0.125f;
        d[2] = v.z * 0.125f; d[3] = v.w * 0.125f;
    }

    float m0 = -1e38f, m1 = -1e38f, l0 = 0.f, l1 = 0.f;
    float o[8][4];
    #pragma unroll
    for (int j = 0; j < 8; j++)
        #pragma unroll
        for (int q = 0; q < 4; q++) o[j][q] = 0.f;

    for (int kt = 0; kt < 4; kt++) {
        __syncthreads();

        for (int t = tid; t < 128 * 16; t += 256) {
            const int rr = t >> 4, c4 = (t & 15) << 2;
            const float* kp = KV + ((size_t)(b * JT_ + kt * 128 + rr)) * (2 * INNER_)
                                 + h * DH_ + c4;
            const float4 k4 = *reinterpret_cast<const float4*>(kp);
            const float4 v4 = *reinterpret_cast<const float4*>(kp + INNER_);
            float* kd = Ks + rr * AT_PAD + c4;
            kd[0] = tf32r(k4.x); kd[1] = tf32r(k4.y);
            kd[2] = tf32r(k4.z); kd[3] = tf32r(k4.w);
            float* vd = Vs + rr * AT_PAD + c4;
            vd[0] = tf32r(v4.x); vd[1] = tf32r(v4.y);
            vd[2] = tf32r(v4.z); vd[3] = tf32r(v4.w);
        }
        for (int t = tid; t < 128 * 4; t += 256) {
            const int r = t >> 2, w = t & 3;
            keepw[t] = KB[((size_t)(b * T1_ + i0 + r)) * 16 + kt * 4 + w];
        }
        __syncthreads();

        uint32_t kw0[4], kw1[4];
        #pragma unroll
        for (int w = 0; w < 4; w++) {
            kw0[w] = keepw[row_g * 4 + w];
            kw1[w] = keepw[(row_g + 8) * 4 + w];
        }

        uint32_t qa[8][4];
        #pragma unroll
        for (int ks = 0; ks < 8; ks++) {
            const float* base = Qs + (warp * 16) * AT_PAD + ks * 8 + q4;
            qa[ks][0] = __float_as_uint(tf32r(base[g * AT_PAD]));
            qa[ks][1] = __float_as_uint(tf32r(base[(g + 8) * AT_PAD]));
            qa[ks][2] = __float_as_uint(tf32r(base[g * AT_PAD + 4]));
            qa[ks][3] = __float_as_uint(tf32r(base[(g + 8) * AT_PAD + 4]));
        }

        float sfr[16][4];
        #pragma unroll
        for (int j = 0; j < 16; j++)
            #pragma unroll
            for (int q = 0; q < 4; q++) sfr[j][q] = 0.f;
        #pragma unroll
        for (int ks = 0; ks < 8; ks++) {
            #pragma unroll
            for (int j = 0; j < 16; j++) {
                uint32_t bb[2];
                const float* kp = Ks + (j * 8 + g) * AT_PAD + ks * 8 + q4;
                bb[0] = __float_as_uint(kp[0]);
                bb[1] = __float_as_uint(kp[4]);
                mma_tf32(sfr[j], qa[ks], bb);
            }
        }

        float mt0 = -1e30f, mt1 = -1e30f;
        #pragma unroll
        for (int j = 0; j < 16; j++) {
            const int cbit = j * 8 + 2 * q4;
            const uint32_t w0 = kw0[j >> 2] >> (cbit & 31);
            const uint32_t w1 = kw1[j >> 2] >> (cbit & 31);
            sfr[j][0] = (w0 & 1u) ? sfr[j][0] : -1e30f;
            sfr[j][1] = (w0 & 2u) ? sfr[j][1] : -1e30f;
            sfr[j][2] = (w1 & 1u) ? sfr[j][2] : -1e30f;
            sfr[j][3] = (w1 & 2u) ? sfr[j][3] : -1e30f;
            mt0 = fmaxf(mt0, fmaxf(sfr[j][0], sfr[j][1]));
            mt1 = fmaxf(mt1, fmaxf(sfr[j][2], sfr[j][3]));
        }
        mt0 = fmaxf(mt0, __shfl_xor_sync(0xffffffffu, mt0, 1));
        mt0 = fmaxf(mt0, __shfl_xor_sync(0xffffffffu, mt0, 2));
        mt1 = fmaxf(mt1, __shfl_xor_sync(0xffffffffu, mt1, 1));
        mt1 = fmaxf(mt1, __shfl_xor_sync(0xffffffffu, mt1, 2));

        const float mn0 = fmaxf(m0, mt0), mn1 = fmaxf(m1, mt1);
        const float al0 = (m0 > -1e37f) ? __expf(m0 - mn0) : 0.f;
        const float al1 = (m1 > -1e37f) ? __expf(m1 - mn1) : 0.f;

        float ps0 = 0.f, ps1 = 0.f;
        #pragma unroll
        for (int j = 0; j < 16; j++) {
            float p0 = (sfr[j][0] > -1e29f) ? __expf(sfr[j][0] - mn0) : 0.f;
            float p1 = (sfr[j][1] > -1e29f) ? __expf(sfr[j][1] - mn0) : 0.f;
            float p2 = (sfr[j][2] > -1e29f) ? __expf(sfr[j][2] - mn1) : 0.f;
            float p3 = (sfr[j][3] > -1e29f) ? __expf(sfr[j][3] - mn1) : 0.f;
            ps0 += p0 + p1; ps1 += p2 + p3;
            sfr[j][0] = tf32r(p0); sfr[j][1] = tf32r(p1);
            sfr[j][2] = tf32r(p2); sfr[j][3] = tf32r(p3);
        }
        ps0 += __shfl_xor_sync(0xffffffffu, ps0, 1);
        ps0 += __shfl_xor_sync(0xffffffffu, ps0, 2);
        ps1 += __shfl_xor_sync(0xffffffffu, ps1, 1);
        ps1 += __shfl_xor_sync(0xffffffffu, ps1, 2);
        l0 = l0 * al0 + ps0;
        l1 = l1 * al1 + ps1;
        m0 = mn0; m1 = mn1;

        #pragma unroll
        for (int j = 0; j < 8; j++) {
            o[j][0] *= al0; o[j][1] *= al0;
            o[j][2] *= al1; o[j][3] *= al1;
        }

        const int srcA = (lane & ~3) | (q4 >> 1);
        const int srcB = srcA + 2;
        const bool odd = (q4 & 1);
        #pragma unroll
        for (int ks = 0; ks < 16; ks++) {
            const float v0a = __shfl_sync(0xffffffffu, sfr[ks][0], srcA);
            const float v1a = __shfl_sync(0xffffffffu, sfr[ks][1], srcA);
            const float v0b = __shfl_sync(0xffffffffu, sfr[ks][0], srcB);
            const float v1b = __shfl_sync(0xffffffffu, sfr[ks][1], srcB);
            const float w0a = __shfl_sync(0xffffffffu, sfr[ks][2], srcA);
            const float w1a = __shfl_sync(0xffffffffu, sfr[ks][3], srcA);
            const float w0b = __shfl_sync(0xffffffffu, sfr[ks][2], srcB);
            const float w1b = __shfl_sync(0xffffffffu, sfr[ks][3], srcB);
            uint32_t a[4];
            a[0] = __float_as_uint(odd ? v1a : v0a);
            a[1] = __float_as_uint(odd ? w1a : w0a);
            a[2] = __float_as_uint(odd ? v1b : v0b);
            a[3] = __float_as_uint(odd ? w1b : w0b);
            const float* vb = Vs + (ks * 8 + q4) * AT_PAD;
            #pragma unroll
            for (int j2 = 0; j2 < 8; j2++) {
                uint32_t bb[2];
                bb[0] = __float_as_uint(vb[j2 * 8 + g]);
                bb[1] = __float_as_uint(vb[4 * AT_PAD + j2 * 8 + g]);
                mma_tf32(o[j2], a, bb);
            }
        }
    }

    const float qm0 = qmask[b * T1_ + i0 + row_g];
    const float qm1 = qmask[b * T1_ + i0 + row_g + 8];
    const float inv0 = (l0 > 0.f) ? qm0 / l0 : 0.f;
    const float inv1 = (l1 > 0.f) ? qm1 / l1 : 0.f;
    __nv_bfloat16* dst0 = AO + ((size_t)(b * T1_ + i0 + row_g)) * INNER_ + h * DH_;
    __nv_bfloat16* dst1 = dst0 + (size_t)8 * INNER_;
    #pragma unroll
    for (int j2 = 0; j2 < 8; j2++) {
        const int cc = j2 * 8 + 2 * q4;
        *reinterpret_cast<__nv_bfloat162*>(dst0 + cc) =
            __floats2bfloat162_rn(o[j2][0] * inv0, o[j2][1] * inv0);
        *reinterpret_cast<__nv_bfloat162*>(dst1 + cc) =
            __floats2bfloat162_rn(o[j2][2] * inv1, o[j2][3] * inv1);
    }
}

// ---------------------------------------------------------------------------
// kernel_launch
// ---------------------------------------------------------------------------
extern "C" void kernel_launch(void* const* d_in, const int* in_sizes, int n_in,
                              void* d_out, int out_size)
{
    const float* qo        = (const float*)d_in[0];
    const float* kvo       = (const float*)d_in[1];
    const void*  amask     = d_in[2];
    const float* qmask     = (const float*)d_in[3];
    const void*  kvmask    = d_in[4];
    const float* ln_g      = (const float*)d_in[5];
    const float* ln_b      = (const float*)d_in[6];
    const float* Wq        = (const float*)d_in[7];
    const float* Wkv       = (const float*)d_in[8];
    const float* Wout      = (const float*)d_in[9];
    const float* attn_gate = (const float*)d_in[10];
    const float* ff_ln_g   = (const float*)d_in[11];
    const float* ff_ln_b   = (const float*)d_in[12];
    const float* W1        = (const float*)d_in[13];
    const float* W2        = (const float*)d_in[14];
    const float* ff_gate   = (const float*)d_in[15];
    float* out = (float*)d_out;

    float *qb, *kvb, *xb;
    unsigned int* kb;
    __nv_bfloat16 *lnh, *aoh, *hh, *kvoh, *wqt, *wkvt, *woutt, *w1t, *w2t;
    cudaGetSymbolAddress((void**)&qb,    g_q);
    cudaGetSymbolAddress((void**)&kvb,   g_kv);
    cudaGetSymbolAddress((void**)&xb,    g_x);
    cudaGetSymbolAddress((void**)&kb,    g_keep);
    cudaGetSymbolAddress((void**)&lnh,   g_ln_h);
    cudaGetSymbolAddress((void**)&aoh,   g_ao_h);
    cudaGetSymbolAddress((void**)&hh,    g_h_h);
    cudaGetSymbolAddress((void**)&kvoh,  g_kvo_h);
    cudaGetSymbolAddress((void**)&wqt,   g_wq_t);
    cudaGetSymbolAddress((void**)&wkvt,  g_wkv_t);
    cudaGetSymbolAddress((void**)&woutt, g_wout_t);
    cudaGetSymbolAddress((void**)&w1t,   g_w1_t);
    cudaGetSymbolAddress((void**)&w2t,   g_w2_t);

    cudaFuncSetAttribute(bf16_gemm_kernel<0, 0>,
        cudaFuncAttributeMaxDynamicSharedMemorySize, GEMM_SMEM);
    cudaFuncSetAttribute(bf16_gemm_kernel<1, 1>,
        cudaFuncAttributeMaxDynamicSharedMemorySize, GEMM_SMEM);
    cudaFuncSetAttribute(bf16_gemm_kernel<2, 0>,
        cudaFuncAttributeMaxDynamicSharedMemorySize, GEMM_SMEM);
    cudaFuncSetAttribute(attn_mma_kernel,
        cudaFuncAttributeMaxDynamicSharedMemorySize, ATTN3_SMEM);

    detect_mask_kernel<<<1, 256>>>((const unsigned int*)amask, 2048);
    pack_keep_kernel<<<(B_ * T1_ * JT_) / 256, 256>>>(amask, kvmask, kb);

    const int ROWS = B_ * T1_;   // 8192
    const dim3 tb(32, 8);

    // conversions: inputs + weights (weights transposed to [N][K] bf16)
    f32_to_bf16_kernel<<<(B_ * JT_ * DIM_ / 4 + 255) / 256, 256>>>(
        kvo, kvoh, B_ * JT_ * DIM_ / 4);
    transpose_bf16_kernel<<<dim3(INNER_ / 32, DIM_ / 32), tb>>>(Wq, wqt, DIM_, INNER_);
    transpose_bf16_kernel<<<dim3(2 * INNER_ / 32, DIM_ / 32), tb>>>(Wkv, wkvt, DIM_, 2 * INNER_);
    transpose_bf16_kernel<<<dim3(DIM_ / 32, INNER_ / 32), tb>>>(Wout, woutt, INNER_, DIM_);
    transpose_bf16_kernel<<<dim3(DFF_ / 32, DIM_ / 32), tb>>>(W1, w1t, DIM_, DFF_);
    transpose_bf16_kernel<<<dim3(DIM_ / 32, DFF_ / 32), tb>>>(W2, w2t, DFF_, DIM_);

    // 1) LN(qo) -> bf16
    ln_kernel<<<ROWS, 256>>>(qo, ln_g, ln_b, lnh);
    // 2) q = LN(qo) @ Wq  (f32 out for attention)
    bf16_gemm_kernel<0, 0><<<dim3(INNER_ / 256, ROWS / 128), 256, GEMM_SMEM>>>(
        lnh, wqt, qb, ROWS, INNER_, DIM_, nullptr, nullptr);
    // 3) kv = kvo @ Wkv  (f32 out)
    bf16_gemm_kernel<0, 0><<<dim3(2 * INNER_ / 256, (B_ * JT_) / 128), 256, GEMM_SMEM>>>(
        kvoh, wkvt, kvb, B_ * JT_, 2 * INNER_, DIM_, nullptr, nullptr);
    // 4) attention -> bf16
    attn_mma_kernel<<<dim3(T1_ / 128, H_, B_), 256, ATTN3_SMEM>>>(
        qb, kvb, kb, qmask, aoh);
    // 5) x = (ao @ Wout)*tanh(g) + qo  (f32)
    bf16_gemm_kernel<2, 0><<<dim3(DIM_ / 256, ROWS / 128), 256, GEMM_SMEM>>>(
        aoh, woutt, xb, ROWS, DIM_, INNER_, attn_gate, qo);
    // 6) LN(x) -> bf16
    ln_kernel<<<ROWS, 256>>>(xb, ff_ln_g, ff_ln_b, lnh);
    // 7) h = gelu(LN(x) @ W1) -> bf16
    bf16_gemm_kernel<1, 1><<<dim3(DFF_ / 256, ROWS / 128), 256, GEMM_SMEM>>>(
        lnh, w1t, hh, ROWS, DFF_, DIM_, nullptr, nullptr);
    // 8) out = (h @ W2)*tanh(g) + x  (f32)
    bf16_gemm_kernel<2, 0><<<dim3(DIM_ / 256, ROWS / 128), 256, GEMM_SMEM>>>(
        hh, w2t, out, ROWS, DIM_, DFF_, ff_gate, xb);
}